// round 1
// baseline (speedup 1.0000x reference)
#include <cuda_runtime.h>

#define FDIM 1024
#define BATCH 8
#define SEQ 2048

// Scratch (allocation-free rule: __device__ globals)
__device__ float g_Q[BATCH * SEQ * FDIM];
__device__ float g_K[BATCH * SEQ * FDIM];
__device__ float g_V[BATCH * SEQ * FDIM];
__device__ float g_S[(size_t)BATCH * SEQ * SEQ];

#define BM 128
#define BN 128
#define BK 16
#define TM 8
#define TN 8

// C[m,n] = alpha * sum_k A[m,k] * B[n,k]  (+ bias[n]); batched via blockIdx.z
__global__ __launch_bounds__(256) void gemm_nt(
    const float* __restrict__ A, const float* __restrict__ B,
    const float* __restrict__ bias, float* __restrict__ C,
    int M, int N, int K, float alpha,
    long long sA, long long sB, long long sC)
{
    __shared__ float As[BK][BM + 4];
    __shared__ float Bs[BK][BN + 4];
    const int z = blockIdx.z;
    A += (long long)z * sA;
    B += (long long)z * sB;
    C += (long long)z * sC;
    const int row0 = blockIdx.x * BM;
    const int col0 = blockIdx.y * BN;
    const int tid = threadIdx.x;
    const int tm0 = (tid >> 4) * TM;
    const int tn0 = (tid & 15) * TN;

    float acc[TM][TN] = {};

    for (int k0 = 0; k0 < K; k0 += BK) {
        // A tile: 128 rows x 16 k, float4 loads, store transposed
        #pragma unroll
        for (int i = 0; i < 2; i++) {
            int idx = tid + i * 256;          // 0..511
            int r  = idx >> 2;                // 0..127
            int kk = (idx & 3) * 4;           // 0,4,8,12
            float4 v = *(const float4*)(A + (long long)(row0 + r) * K + k0 + kk);
            As[kk + 0][r] = v.x; As[kk + 1][r] = v.y;
            As[kk + 2][r] = v.z; As[kk + 3][r] = v.w;
        }
        // B tile (stored [N,K]): same pattern
        #pragma unroll
        for (int i = 0; i < 2; i++) {
            int idx = tid + i * 256;
            int r  = idx >> 2;
            int kk = (idx & 3) * 4;
            float4 v = *(const float4*)(B + (long long)(col0 + r) * K + k0 + kk);
            Bs[kk + 0][r] = v.x; Bs[kk + 1][r] = v.y;
            Bs[kk + 2][r] = v.z; Bs[kk + 3][r] = v.w;
        }
        __syncthreads();

        #pragma unroll
        for (int kk = 0; kk < BK; kk++) {
            float a[TM], b[TN];
            #pragma unroll
            for (int i = 0; i < TM; i++) a[i] = As[kk][tm0 + i];
            #pragma unroll
            for (int j = 0; j < TN; j++) b[j] = Bs[kk][tn0 + j];
            #pragma unroll
            for (int i = 0; i < TM; i++)
                #pragma unroll
                for (int j = 0; j < TN; j++)
                    acc[i][j] += a[i] * b[j];
        }
        __syncthreads();
    }

    #pragma unroll
    for (int i = 0; i < TM; i++) {
        long long r = row0 + tm0 + i;
        #pragma unroll
        for (int j = 0; j < TN; j++) {
            float v = acc[i][j] * alpha;
            if (bias) v += bias[col0 + tn0 + j];
            C[r * N + col0 + tn0 + j] = v;
        }
    }
}

// C[m,n] = alpha * sum_k A[m,k] * B[k,n]; batched via blockIdx.z
__global__ __launch_bounds__(256) void gemm_nn(
    const float* __restrict__ A, const float* __restrict__ B,
    float* __restrict__ C,
    int M, int N, int K, float alpha,
    long long sA, long long sB, long long sC)
{
    __shared__ float As[BK][BM + 4];
    __shared__ float Bs[BK][BN + 4];
    const int z = blockIdx.z;
    A += (long long)z * sA;
    B += (long long)z * sB;
    C += (long long)z * sC;
    const int row0 = blockIdx.x * BM;
    const int col0 = blockIdx.y * BN;
    const int tid = threadIdx.x;
    const int tm0 = (tid >> 4) * TM;
    const int tn0 = (tid & 15) * TN;

    float acc[TM][TN] = {};

    for (int k0 = 0; k0 < K; k0 += BK) {
        #pragma unroll
        for (int i = 0; i < 2; i++) {
            int idx = tid + i * 256;
            int r  = idx >> 2;
            int kk = (idx & 3) * 4;
            float4 v = *(const float4*)(A + (long long)(row0 + r) * K + k0 + kk);
            As[kk + 0][r] = v.x; As[kk + 1][r] = v.y;
            As[kk + 2][r] = v.z; As[kk + 3][r] = v.w;
        }
        // B tile (stored [K,N]): rows=k (16), cols=n (128)
        #pragma unroll
        for (int i = 0; i < 2; i++) {
            int idx = tid + i * 256;          // 0..511
            int r  = idx >> 5;                // 0..15 (k within tile)
            int cc = (idx & 31) * 4;          // 0..124
            float4 v = *(const float4*)(B + (long long)(k0 + r) * N + col0 + cc);
            *(float4*)&Bs[r][cc] = v;         // row stride (BN+4)*4B = 528B, 16B-aligned
        }
        __syncthreads();

        #pragma unroll
        for (int kk = 0; kk < BK; kk++) {
            float a[TM], b[TN];
            #pragma unroll
            for (int i = 0; i < TM; i++) a[i] = As[kk][tm0 + i];
            #pragma unroll
            for (int j = 0; j < TN; j++) b[j] = Bs[kk][tn0 + j];
            #pragma unroll
            for (int i = 0; i < TM; i++)
                #pragma unroll
                for (int j = 0; j < TN; j++)
                    acc[i][j] += a[i] * b[j];
        }
        __syncthreads();
    }

    #pragma unroll
    for (int i = 0; i < TM; i++) {
        long long r = row0 + tm0 + i;
        #pragma unroll
        for (int j = 0; j < TN; j++)
            C[r * N + col0 + tn0 + j] = acc[i][j] * alpha;
    }
}

// One CTA per row of 2048 scores: max -> exp -> sum -> normalize, single pass over gmem
__global__ __launch_bounds__(256) void softmax_rows(float* __restrict__ S)
{
    __shared__ float red[256];
    float* p = S + (long long)blockIdx.x * SEQ;
    const int tid = threadIdx.x;

    float v[8];
    float mx = -1e30f;
    #pragma unroll
    for (int i = 0; i < 8; i++) {
        v[i] = p[tid + i * 256];
        mx = fmaxf(mx, v[i]);
    }
    red[tid] = mx;
    __syncthreads();
    for (int s = 128; s > 0; s >>= 1) {
        if (tid < s) red[tid] = fmaxf(red[tid], red[tid + s]);
        __syncthreads();
    }
    mx = red[0];
    __syncthreads();

    float sum = 0.0f;
    #pragma unroll
    for (int i = 0; i < 8; i++) {
        v[i] = __expf(v[i] - mx);
        sum += v[i];
    }
    red[tid] = sum;
    __syncthreads();
    for (int s = 128; s > 0; s >>= 1) {
        if (tid < s) red[tid] += red[tid + s];
        __syncthreads();
    }
    float inv = 1.0f / red[0];

    #pragma unroll
    for (int i = 0; i < 8; i++)
        p[tid + i * 256] = v[i] * inv;
}

extern "C" void kernel_launch(void* const* d_in, const int* in_sizes, int n_in,
                              void* d_out, int out_size)
{
    const float* x  = (const float*)d_in[0];
    const float* Wq = (const float*)d_in[1];
    const float* bq = (const float*)d_in[2];
    const float* Wk = (const float*)d_in[3];
    const float* bk = (const float*)d_in[4];
    const float* Wv = (const float*)d_in[5];
    const float* bv = (const float*)d_in[6];
    float* out = (float*)d_out;

    float *Q, *K, *V, *S;
    cudaGetSymbolAddress((void**)&Q, g_Q);
    cudaGetSymbolAddress((void**)&K, g_K);
    cudaGetSymbolAddress((void**)&V, g_V);
    cudaGetSymbolAddress((void**)&S, g_S);

    const int M = BATCH * SEQ;           // 16384
    dim3 blk(256);

    // QKV projections: y = x @ W^T + b   (NT GEMM, M=16384, N=1024, K=1024)
    dim3 g1(M / BM, FDIM / BN, 1);
    gemm_nt<<<g1, blk>>>(x, Wq, bq, Q, M, FDIM, FDIM, 1.0f, 0, 0, 0);
    gemm_nt<<<g1, blk>>>(x, Wk, bk, K, M, FDIM, FDIM, 1.0f, 0, 0, 0);
    gemm_nt<<<g1, blk>>>(x, Wv, bv, V, M, FDIM, FDIM, 1.0f, 0, 0, 0);

    // scores = Q @ K^T / 32   (batched NT, per-batch 2048x2048x1024)
    dim3 g2(SEQ / BM, SEQ / BN, BATCH);
    gemm_nt<<<g2, blk>>>(Q, K, nullptr, S, SEQ, SEQ, FDIM, 0.03125f,
                         (long long)SEQ * FDIM, (long long)SEQ * FDIM,
                         (long long)SEQ * SEQ);

    // softmax over last dim
    softmax_rows<<<BATCH * SEQ, 256>>>(S);

    // out = P @ V   (batched NN, per-batch 2048x1024x2048)
    dim3 g3(SEQ / BM, FDIM / BN, BATCH);
    gemm_nn<<<g3, blk>>>(S, V, out, SEQ, FDIM, SEQ, 1.0f,
                         (long long)SEQ * SEQ, (long long)SEQ * FDIM,
                         (long long)SEQ * FDIM);
}

// round 3
// speedup vs baseline: 2.0492x; 2.0492x over previous
#include <cuda_runtime.h>
#include <cuda_bf16.h>
#include <cstdint>

#define FDIM 1024
#define BATCH 8
#define SEQ 2048
#define MTOT (BATCH * SEQ)   // 16384

// ---------------- scratch (__device__ globals; no allocation allowed) ----------------
__device__ __nv_bfloat16 g_xh[MTOT * FDIM], g_xl[MTOT * FDIM];
__device__ __nv_bfloat16 g_Wh[3][FDIM * FDIM], g_Wl[3][FDIM * FDIM];
__device__ __nv_bfloat16 g_Qh[MTOT * FDIM], g_Ql[MTOT * FDIM];
__device__ __nv_bfloat16 g_Kh[MTOT * FDIM], g_Kl[MTOT * FDIM];
__device__ __nv_bfloat16 g_Vh[MTOT * FDIM], g_Vl[MTOT * FDIM];
__device__ __nv_bfloat16 g_Vth[BATCH * FDIM * SEQ], g_Vtl[BATCH * FDIM * SEQ];
__device__ float g_S[(size_t)BATCH * SEQ * SEQ];
__device__ __nv_bfloat16 g_Ph[(size_t)BATCH * SEQ * SEQ], g_Pl[(size_t)BATCH * SEQ * SEQ];

// ---------------- PTX helpers (all plain-sm_103-safe: ldmatrix/mma.sync/cp.async) ----
__device__ __forceinline__ uint32_t smem_to_u32(const void* p) {
    uint32_t a;
    asm("{ .reg .u64 t; cvta.to.shared.u64 t, %1; cvt.u32.u64 %0, t; }" : "=r"(a) : "l"(p));
    return a;
}
__device__ __forceinline__ void cp_async16(uint32_t dst, const void* src) {
    asm volatile("cp.async.cg.shared.global [%0], [%1], 16;" :: "r"(dst), "l"(src));
}
#define CP_COMMIT() asm volatile("cp.async.commit_group;" ::: "memory")
#define CP_WAIT0()  asm volatile("cp.async.wait_group 0;" ::: "memory")
#define CP_WAIT1()  asm volatile("cp.async.wait_group 1;" ::: "memory")

__device__ __forceinline__ void ldm4(uint32_t (&r)[4], uint32_t addr) {
    asm volatile("ldmatrix.sync.aligned.m8n8.x4.shared.b16 {%0,%1,%2,%3}, [%4];"
                 : "=r"(r[0]), "=r"(r[1]), "=r"(r[2]), "=r"(r[3]) : "r"(addr));
}
__device__ __forceinline__ void mma16816(float (&d)[4], const uint32_t (&a)[4],
                                         uint32_t b0, uint32_t b1) {
    asm volatile("mma.sync.aligned.m16n8k16.row.col.f32.bf16.bf16.f32 "
                 "{%0,%1,%2,%3}, {%4,%5,%6,%7}, {%8,%9}, {%0,%1,%2,%3};"
                 : "+f"(d[0]), "+f"(d[1]), "+f"(d[2]), "+f"(d[3])
                 : "r"(a[0]), "r"(a[1]), "r"(a[2]), "r"(a[3]), "r"(b0), "r"(b1));
}

// ---------------- GEMM config ----------------
// CTA tile 128x128, BK=32. 8 warps, each 64(m) x 32(n).
// SMEM per buffer: Ah, Al, Bh, Bl tiles of 128 rows x 32 bf16, row-padded to 40 bf16 (80 B).
#define TILE_B   10240            // 128*40*2
#define BUF_B    (4 * TILE_B)     // 40960
#define SMEM_SZ  (2 * BUF_B)      // 81920

__device__ __forceinline__ void load_chunk(
    uint32_t smem0, int buf, int tid,
    const __nv_bfloat16* Ah, const __nv_bfloat16* Al,
    const __nv_bfloat16* Bh, const __nv_bfloat16* Bl,
    long long kofs, int Kd)
{
    const __nv_bfloat16* srcs[4] = { Ah + kofs, Al + kofs, Bh + kofs, Bl + kofs };
    uint32_t base = smem0 + buf * BUF_B;
    #pragma unroll
    for (int t = 0; t < 4; t++) {
        uint32_t tb = base + t * TILE_B;
        #pragma unroll
        for (int i = 0; i < 2; i++) {
            int u = tid + i * 256;          // 0..511
            int row = u >> 2;               // 0..127
            int seg = u & 3;                // 16B segment within 64B row
            cp_async16(tb + row * 80 + seg * 16,
                       srcs[t] + (long long)row * Kd + seg * 8);
        }
    }
    CP_COMMIT();
}

// C(Mx N) = alpha * A(MxK) @ B(NxK)^T [+ bias]; split-bf16 3-term HMMA.
// mode 0: outHi/outLo bf16 (+bias). mode 1/2: outF fp32.
__global__ __launch_bounds__(256, 1) void gemm_mma(
    const __nv_bfloat16* __restrict__ Ahi, const __nv_bfloat16* __restrict__ Alo,
    const __nv_bfloat16* __restrict__ Bhi, const __nv_bfloat16* __restrict__ Blo,
    const float* __restrict__ bias,
    __nv_bfloat16* __restrict__ outHi, __nv_bfloat16* __restrict__ outLo,
    float* __restrict__ outF,
    int N, int Kd, float alpha, int mode,
    long long sA, long long sB, long long sC)
{
    extern __shared__ char smem[];
    const uint32_t smem0 = smem_to_u32(smem);
    const int tid = threadIdx.x;
    const int wid = tid >> 5;
    const int lane = tid & 31;
    const int z = blockIdx.z;
    const long long row0 = (long long)blockIdx.x * 128;
    const long long col0 = (long long)blockIdx.y * 128;

    const __nv_bfloat16* Ah = Ahi + (long long)z * sA + row0 * Kd;
    const __nv_bfloat16* Al = Alo + (long long)z * sA + row0 * Kd;
    const __nv_bfloat16* Bh = Bhi + (long long)z * sB + col0 * Kd;
    const __nv_bfloat16* Bl = Blo + (long long)z * sB + col0 * Kd;

    const int warp_m0 = (wid >> 2) * 64;   // 0 or 64
    const int warp_n0 = (wid & 3) * 32;    // 0,32,64,96

    // per-lane ldmatrix byte offset: (lane&15) rows + k-half select
    const uint32_t lmofs = (uint32_t)(lane & 15) * 80 + (uint32_t)(lane >> 4) * 16;

    float acc[4][4][4];
    #pragma unroll
    for (int a = 0; a < 4; a++)
        #pragma unroll
        for (int b = 0; b < 4; b++)
            #pragma unroll
            for (int cI = 0; cI < 4; cI++) acc[a][b][cI] = 0.0f;

    const int NC = Kd >> 5;   // BK = 32

    load_chunk(smem0, 0, tid, Ah, Al, Bh, Bl, 0, Kd);
    load_chunk(smem0, 1, tid, Ah, Al, Bh, Bl, 32, Kd);

    for (int c = 0; c < NC; c++) {
        if (c < NC - 1) CP_WAIT1(); else CP_WAIT0();
        __syncthreads();

        const uint32_t bufb = smem0 + (c & 1) * BUF_B;
        const uint32_t tAh = bufb,             tAl = bufb + TILE_B;
        const uint32_t tBh = bufb + 2 * TILE_B, tBl = bufb + 3 * TILE_B;

        #pragma unroll
        for (int ks = 0; ks < 2; ks++) {
            uint32_t ah[4][4], al[4][4], bh[2][4], bl[2][4];
            #pragma unroll
            for (int g = 0; g < 4; g++) {
                uint32_t o = (uint32_t)(warp_m0 + g * 16) * 80 + ks * 32 + lmofs;
                ldm4(ah[g], tAh + o);
                ldm4(al[g], tAl + o);
            }
            #pragma unroll
            for (int g = 0; g < 2; g++) {
                uint32_t o = (uint32_t)(warp_n0 + g * 16) * 80 + ks * 32 + lmofs;
                ldm4(bh[g], tBh + o);
                ldm4(bl[g], tBl + o);
            }
            #pragma unroll
            for (int mf = 0; mf < 4; mf++)
                #pragma unroll
                for (int nf = 0; nf < 4; nf++) {
                    const int g = nf >> 1, p = nf & 1;
                    mma16816(acc[mf][nf], ah[mf], bh[g][p], bh[g][p + 2]);
                    mma16816(acc[mf][nf], ah[mf], bl[g][p], bl[g][p + 2]);
                    mma16816(acc[mf][nf], al[mf], bh[g][p], bh[g][p + 2]);
                }
        }

        __syncthreads();
        if (c + 2 < NC)
            load_chunk(smem0, c & 1, tid, Ah, Al, Bh, Bl, (long long)(c + 2) * 32, Kd);
    }

    // ---- epilogue: fragments -> gmem ----
    // lane holds, for frag (mf,nf): rows mf*16 + lane/4 (+8), cols nf*8 + 2*(lane%4) (+1)
    const int rbase = warp_m0 + (lane >> 2);
    const int cbase = warp_n0 + 2 * (lane & 3);
    #pragma unroll
    for (int mf = 0; mf < 4; mf++) {
        #pragma unroll
        for (int nf = 0; nf < 4; nf++) {
            #pragma unroll
            for (int h = 0; h < 2; h++) {   // h=0: row, h=1: row+8
                long long r = row0 + rbase + mf * 16 + h * 8;
                long long cc = col0 + cbase + nf * 8;
                float f0 = acc[mf][nf][h * 2 + 0] * alpha;
                float f1 = acc[mf][nf][h * 2 + 1] * alpha;
                if (mode == 0) {
                    f0 += bias[cc];
                    f1 += bias[cc + 1];
                    __nv_bfloat16 h0 = __float2bfloat16(f0);
                    __nv_bfloat16 l0 = __float2bfloat16(f0 - __bfloat162float(h0));
                    __nv_bfloat16 h1 = __float2bfloat16(f1);
                    __nv_bfloat16 l1 = __float2bfloat16(f1 - __bfloat162float(h1));
                    long long o = r * (long long)N + cc;
                    __nv_bfloat162 ph; ph.x = h0; ph.y = h1;
                    __nv_bfloat162 pl; pl.x = l0; pl.y = l1;
                    *(__nv_bfloat162*)(outHi + o) = ph;
                    *(__nv_bfloat162*)(outLo + o) = pl;
                } else {
                    long long o = (long long)z * sC + r * (long long)N + cc;
                    *(float2*)(outF + o) = make_float2(f0, f1);
                }
            }
        }
    }
}

// split fp32 -> (hi, lo) bf16
__global__ __launch_bounds__(256) void split_f32(
    const float* __restrict__ src, __nv_bfloat16* __restrict__ hi,
    __nv_bfloat16* __restrict__ lo, int n)
{
    int i = (blockIdx.x * 256 + threadIdx.x) * 4;
    if (i >= n) return;
    float4 v = *(const float4*)(src + i);
    float f[4] = { v.x, v.y, v.z, v.w };
    __nv_bfloat16 h[4], l[4];
    #pragma unroll
    for (int k = 0; k < 4; k++) {
        h[k] = __float2bfloat16(f[k]);
        l[k] = __float2bfloat16(f[k] - __bfloat162float(h[k]));
    }
    __nv_bfloat162 h0; h0.x = h[0]; h0.y = h[1];
    __nv_bfloat162 h1; h1.x = h[2]; h1.y = h[3];
    __nv_bfloat162 l0; l0.x = l[0]; l0.y = l[1];
    __nv_bfloat162 l1; l1.x = l[2]; l1.y = l[3];
    *(__nv_bfloat162*)(hi + i) = h0; *(__nv_bfloat162*)(hi + i + 2) = h1;
    *(__nv_bfloat162*)(lo + i) = l0; *(__nv_bfloat162*)(lo + i + 2) = l1;
}

// Vt[b][d][s] = V[b*SEQ+s][d]
__global__ __launch_bounds__(256) void transpose_v(
    const __nv_bfloat16* __restrict__ Vh, const __nv_bfloat16* __restrict__ Vl,
    __nv_bfloat16* __restrict__ Vth, __nv_bfloat16* __restrict__ Vtl)
{
    __shared__ __nv_bfloat16 th[32][33], tl[32][33];
    const int b = blockIdx.z;
    const int s0 = blockIdx.x * 32, d0 = blockIdx.y * 32;
    const int tx = threadIdx.x, ty = threadIdx.y;
    #pragma unroll
    for (int j = 0; j < 4; j++) {
        int r = ty + j * 8;
        long long src = (long long)(b * SEQ + s0 + r) * FDIM + d0 + tx;
        th[r][tx] = Vh[src];
        tl[r][tx] = Vl[src];
    }
    __syncthreads();
    #pragma unroll
    for (int j = 0; j < 4; j++) {
        int r = ty + j * 8;
        long long dst = (long long)(b * FDIM + d0 + r) * SEQ + s0 + tx;
        Vth[dst] = th[tx][r];
        Vtl[dst] = tl[tx][r];
    }
}

// row softmax: S fp32 -> P hi/lo bf16
__global__ __launch_bounds__(256) void softmax_rows(
    const float* __restrict__ S, __nv_bfloat16* __restrict__ Ph,
    __nv_bfloat16* __restrict__ Pl)
{
    __shared__ float red[256];
    const long long roff = (long long)blockIdx.x * SEQ;
    const float* p = S + roff;
    const int tid = threadIdx.x;

    float v[8];
    float mx = -1e30f;
    #pragma unroll
    for (int i = 0; i < 8; i++) { v[i] = p[tid + i * 256]; mx = fmaxf(mx, v[i]); }
    red[tid] = mx;
    __syncthreads();
    for (int s = 128; s > 0; s >>= 1) {
        if (tid < s) red[tid] = fmaxf(red[tid], red[tid + s]);
        __syncthreads();
    }
    mx = red[0];
    __syncthreads();

    float sum = 0.0f;
    #pragma unroll
    for (int i = 0; i < 8; i++) { v[i] = __expf(v[i] - mx); sum += v[i]; }
    red[tid] = sum;
    __syncthreads();
    for (int s = 128; s > 0; s >>= 1) {
        if (tid < s) red[tid] += red[tid + s];
        __syncthreads();
    }
    float inv = 1.0f / red[0];

    #pragma unroll
    for (int i = 0; i < 8; i++) {
        float w = v[i] * inv;
        __nv_bfloat16 h = __float2bfloat16(w);
        __nv_bfloat16 l = __float2bfloat16(w - __bfloat162float(h));
        Ph[roff + tid + i * 256] = h;
        Pl[roff + tid + i * 256] = l;
    }
}

extern "C" void kernel_launch(void* const* d_in, const int* in_sizes, int n_in,
                              void* d_out, int out_size)
{
    const float* x  = (const float*)d_in[0];
    const float* Wq = (const float*)d_in[1];
    const float* bq = (const float*)d_in[2];
    const float* Wk = (const float*)d_in[3];
    const float* bk = (const float*)d_in[4];
    const float* Wv = (const float*)d_in[5];
    const float* bv = (const float*)d_in[6];
    float* out = (float*)d_out;

    cudaFuncSetAttribute(gemm_mma, cudaFuncAttributeMaxDynamicSharedMemorySize, SMEM_SZ);

    __nv_bfloat16 *xh, *xl, *Wh, *Wl, *Qh, *Ql, *Kh, *Kl, *Vh, *Vl, *Vth, *Vtl, *Ph, *Pl;
    float* S;
    cudaGetSymbolAddress((void**)&xh, g_xh);   cudaGetSymbolAddress((void**)&xl, g_xl);
    cudaGetSymbolAddress((void**)&Wh, g_Wh);   cudaGetSymbolAddress((void**)&Wl, g_Wl);
    cudaGetSymbolAddress((void**)&Qh, g_Qh);   cudaGetSymbolAddress((void**)&Ql, g_Ql);
    cudaGetSymbolAddress((void**)&Kh, g_Kh);   cudaGetSymbolAddress((void**)&Kl, g_Kl);
    cudaGetSymbolAddress((void**)&Vh, g_Vh);   cudaGetSymbolAddress((void**)&Vl, g_Vl);
    cudaGetSymbolAddress((void**)&Vth, g_Vth); cudaGetSymbolAddress((void**)&Vtl, g_Vtl);
    cudaGetSymbolAddress((void**)&Ph, g_Ph);   cudaGetSymbolAddress((void**)&Pl, g_Pl);
    cudaGetSymbolAddress((void**)&S, g_S);

    const int NX = MTOT * FDIM;
    const int NW = FDIM * FDIM;
    const long long WSZ = (long long)FDIM * FDIM;

    split_f32<<<NX / 4 / 256, 256>>>(x, xh, xl, NX);
    split_f32<<<NW / 4 / 256, 256>>>(Wq, Wh + 0 * WSZ, Wl + 0 * WSZ, NW);
    split_f32<<<NW / 4 / 256, 256>>>(Wk, Wh + 1 * WSZ, Wl + 1 * WSZ, NW);
    split_f32<<<NW / 4 / 256, 256>>>(Wv, Wh + 2 * WSZ, Wl + 2 * WSZ, NW);

    // QKV projections
    dim3 g1(MTOT / 128, FDIM / 128, 1);
    gemm_mma<<<g1, 256, SMEM_SZ>>>(xh, xl, Wh + 0 * WSZ, Wl + 0 * WSZ, bq, Qh, Ql, nullptr,
                                   FDIM, FDIM, 1.0f, 0, 0, 0, 0);
    gemm_mma<<<g1, 256, SMEM_SZ>>>(xh, xl, Wh + 1 * WSZ, Wl + 1 * WSZ, bk, Kh, Kl, nullptr,
                                   FDIM, FDIM, 1.0f, 0, 0, 0, 0);
    gemm_mma<<<g1, 256, SMEM_SZ>>>(xh, xl, Wh + 2 * WSZ, Wl + 2 * WSZ, bv, Vh, Vl, nullptr,
                                   FDIM, FDIM, 1.0f, 0, 0, 0, 0);

    // scores = Q @ K^T / 32
    dim3 g2(SEQ / 128, SEQ / 128, BATCH);
    gemm_mma<<<g2, 256, SMEM_SZ>>>(Qh, Ql, Kh, Kl, nullptr, nullptr, nullptr, S,
                                   SEQ, FDIM, 0.03125f, 1,
                                   (long long)SEQ * FDIM, (long long)SEQ * FDIM,
                                   (long long)SEQ * SEQ);

    transpose_v<<<dim3(SEQ / 32, FDIM / 32, BATCH), dim3(32, 8)>>>(Vh, Vl, Vth, Vtl);

    softmax_rows<<<BATCH * SEQ, 256>>>(S, Ph, Pl);

    // out = P @ Vt^T
    dim3 g3(SEQ / 128, FDIM / 128, BATCH);
    gemm_mma<<<g3, 256, SMEM_SZ>>>(Ph, Pl, Vth, Vtl, nullptr, nullptr, nullptr, out,
                                   FDIM, SEQ, 1.0f, 2,
                                   (long long)SEQ * SEQ, (long long)FDIM * SEQ,
                                   (long long)SEQ * FDIM);
}